// round 14
// baseline (speedup 1.0000x reference)
#include <cuda_runtime.h>
#include <cuda_fp16.h>
#include <cstdint>

#define TT 16
#define CC 768
#define SS 2048
#define NHEAD 12
#define HDIM 64
#define NQKV 2304

// Scratch (device globals; no allocation allowed)
__device__ __half g_xh[(size_t)TT * CC * SS];          // fp16(x * invrms * w1), [t][k][s]
__device__ __half g_wh_in[(size_t)NQKV * CC];          // fp16(Win)
__device__ __half g_wh_out[(size_t)CC * CC];           // fp16(Wout)
__device__ __half g_qkv_h[(size_t)32768 * NQKV];       // [m=t*2048+s][n] fp16
__device__ __half g_att_h[(size_t)TT * CC * SS];       // [t][c][s] fp16

__device__ __forceinline__ uint32_t packh(float lo, float hi) {
    __half2 h = __floats2half2_rn(lo, hi);
    return *(uint32_t*)&h;
}

__device__ __forceinline__ void mma_f16(float* d, const uint32_t* a, uint32_t b0, uint32_t b1) {
    asm volatile(
        "mma.sync.aligned.m16n8k16.row.col.f32.f16.f16.f32 "
        "{%0,%1,%2,%3}, {%4,%5,%6,%7}, {%8,%9}, {%0,%1,%2,%3};"
        : "+f"(d[0]), "+f"(d[1]), "+f"(d[2]), "+f"(d[3])
        : "r"(a[0]), "r"(a[1]), "r"(a[2]), "r"(a[3]), "r"(b0), "r"(b1));
}

__device__ __forceinline__ void cp16(uint32_t dst, const void* src) {
    asm volatile("cp.async.cg.shared.global [%0], [%1], 16;" :: "r"(dst), "l"(src));
}
#define CP_COMMIT() asm volatile("cp.async.commit_group;" ::: "memory")
#define CP_WAIT1()  asm volatile("cp.async.wait_group 1;" ::: "memory")

__device__ __forceinline__ void ldsm4(uint32_t* r, uint32_t addr) {
    asm volatile("ldmatrix.sync.aligned.m8n8.x4.shared.b16 {%0,%1,%2,%3}, [%4];"
        : "=r"(r[0]), "=r"(r[1]), "=r"(r[2]), "=r"(r[3]) : "r"(addr));
}
__device__ __forceinline__ void ldsm4t(uint32_t* r, uint32_t addr) {
    asm volatile("ldmatrix.sync.aligned.m8n8.x4.trans.shared.b16 {%0,%1,%2,%3}, [%4];"
        : "=r"(r[0]), "=r"(r[1]), "=r"(r[2]), "=r"(r[3]) : "r"(addr));
}

// ---------------- 1) group RMS + fp16 conversion (fused) ----------------
__global__ __launch_bounds__(256)
void rms_conv_kernel(const float* __restrict__ x, const float* __restrict__ w1) {
    int b = blockIdx.x;
    int t = b / NHEAD, g = b - t * NHEAD;
    const float4* p = (const float4*)(x + (size_t)b * 64 * SS);
    float s = 0.f;
    for (int i = threadIdx.x; i < (64 * SS) / 4; i += 256) {
        float4 v = p[i];
        s += v.x * v.x + v.y * v.y + v.z * v.z + v.w * v.w;
    }
    #pragma unroll
    for (int m = 16; m; m >>= 1) s += __shfl_xor_sync(0xffffffffu, s, m);
    __shared__ float red[8];
    __shared__ float s_inv;
    if ((threadIdx.x & 31) == 0) red[threadIdx.x >> 5] = s;
    __syncthreads();
    if (threadIdx.x == 0) {
        float tot = 0.f;
        #pragma unroll
        for (int j = 0; j < 8; j++) tot += red[j];
        s_inv = rsqrtf(tot * (1.0f / (64.0f * SS)) + 1e-6f);
    }
    __syncthreads();
    const float inv = s_inv;

    for (int i = threadIdx.x; i < (64 * SS) / 8; i += 256) {
        int row = i >> 8;
        int off = (i & 255) * 8;
        float sc = inv * w1[g * 64 + row];
        const float4* src = (const float4*)(x + ((size_t)b * 64 + row) * SS + off);
        float4 a = src[0], c = src[1];
        uint32_t o[4] = {packh(a.x * sc, a.y * sc), packh(a.z * sc, a.w * sc),
                         packh(c.x * sc, c.y * sc), packh(c.z * sc, c.w * sc)};
        *(uint4*)(g_xh + ((size_t)(t * CC + g * 64 + row)) * SS + off) = *(uint4*)o;
    }
}

// ---------------- 1c) prep: fp16 weight copies ----------------
__global__ __launch_bounds__(256)
void convw_kernel(const float* __restrict__ src, __half* __restrict__ dst, int n4) {
    int i = blockIdx.x * blockDim.x + threadIdx.x;
    if (i < n4) {
        float4 v = ((const float4*)src)[i];
        uint32_t o[2] = {packh(v.x, v.y), packh(v.z, v.w)};
        *(uint2*)(dst + (size_t)i * 4) = *(uint2*)o;
    }
}

// ---------------- 2/4) mma.sync fp16 GEMM, CTA 256x128, warp tile 64x64 ----------------
// 8 warps (4 m x 2 n), K-chunk 32, 3-stage cp.async, 1 CTA/SM.
// As[k][m]: 32 x 264 halves/stage (stride 528B ≡ 16 mod 128 — ldsm4t conflict-free).
// Bs[n][k]: 128 x 40 halves/stage (stride 80B — ldsm4 conflict-free).
#define NKIT2 24
#define APADH 264
#define ASTG_BYTES (32 * APADH * 2)         // 16896
#define BPADH 40
#define BSTG_BYTES (128 * BPADH * 2)        // 10240
#define GEMM_SMEM (3 * (ASTG_BYTES + BSTG_BYTES))   // 81408

template <int MODE>
__global__ __launch_bounds__(256, 1)
void mma_gemm(const float* __restrict__ x, const float* __restrict__ bias,
              float* __restrict__ Cout, int Nn) {
    extern __shared__ __align__(16) char smem_raw[];
    __half (*As)[32][APADH]  = (__half (*)[32][APADH])smem_raw;
    __half (*Bs)[128][BPADH] = (__half (*)[128][BPADH])(smem_raw + 3 * ASTG_BYTES);
    float (*stg)[16][68]     = (float (*)[16][68])smem_raw;   // MODE 1 epilogue overlay

    const int tid  = threadIdx.x;
    const int wid  = tid >> 5;
    const int lane = tid & 31;
    const int wm   = (wid >> 1) * 64;      // 4 warps over m (256)
    const int wn   = (wid & 1) * 64;       // 2 warps over n (128)
    const int lq   = lane >> 2;
    const int lr   = lane & 3;

    const int m0 = blockIdx.y * 256;
    const int n0 = blockIdx.x * 128;
    const int t  = m0 >> 11;
    const int s0 = m0 & 2047;

    const __half* Asrc = (MODE == 0) ? g_xh : g_att_h;
    const __half* Bsrc = (MODE == 0) ? g_wh_in : g_wh_out;

    // ldmatrix lane base addresses (stage 0)
    const int kA_l = ((lane >> 4) << 3) + (lane & 7);
    const int mOff = (((lane >> 3) & 1) << 3);
    const int nB_l = (((lane >> 3) & 1) << 3) + (lane & 7);
    const int kB_l = ((lane >> 4) << 3);
    uint32_t aA0[4], aB0[4];
    #pragma unroll
    for (int im = 0; im < 4; im++)
        aA0[im] = (uint32_t)__cvta_generic_to_shared(&As[0][kA_l][wm + im * 16 + mOff]);
    #pragma unroll
    for (int bg = 0; bg < 4; bg++)
        aB0[bg] = (uint32_t)__cvta_generic_to_shared(&Bs[0][wn + bg * 16 + nB_l][kB_l]);

    float acc[4][8][4];
    #pragma unroll
    for (int i = 0; i < 4; i++)
        #pragma unroll
        for (int j = 0; j < 8; j++)
            #pragma unroll
            for (int c = 0; c < 4; c++) acc[i][j][c] = 0.f;

    auto issueA = [&](int k0, int p) {     // 32 rows x 256 halves = 1024 chunks
        #pragma unroll
        for (int r = 0; r < 4; r++) {
            int o = tid * 4 + r;
            int row = o >> 5;
            int ch  = (o & 31) * 8;
            cp16((uint32_t)__cvta_generic_to_shared(&As[p][row][ch]),
                 Asrc + ((size_t)(t * CC + k0 + row)) * SS + s0 + ch);
        }
    };
    auto issueB = [&](int k0, int p) {     // 128 rows x 32 halves = 512 chunks
        #pragma unroll
        for (int r = 0; r < 2; r++) {
            int o = tid * 2 + r;
            int row = o >> 2;
            int ch  = (o & 3) * 8;
            cp16((uint32_t)__cvta_generic_to_shared(&Bs[p][row][ch]),
                 Bsrc + (size_t)(n0 + row) * CC + k0 + ch);
        }
    };

    // prologue: stages 0,1 as groups g0,g1
    #pragma unroll
    for (int p = 0; p < 2; p++) {
        issueA(p * 32, p);
        issueB(p * 32, p);
        CP_COMMIT();
    }

    for (int i = 0; i < NKIT2; i++) {
        const int p = i % 3;
        CP_WAIT1();
        __syncthreads();

        const uint32_t aoff = (uint32_t)(p * ASTG_BYTES);
        const uint32_t boff = (uint32_t)(p * BSTG_BYTES);

        // ks = 0 frags
        uint32_t af[4][4], bf[4][4];
        #pragma unroll
        for (int im = 0; im < 4; im++) ldsm4t(af[im], aA0[im] + aoff);
        #pragma unroll
        for (int bg = 0; bg < 4; bg++) ldsm4(bf[bg], aB0[bg] + boff);

        // prefetch next stage
        if (i + 2 < NKIT2) {
            const int pn = (i + 2) % 3;
            issueA((i + 2) * 32, pn);
            issueB((i + 2) * 32, pn);
        }
        CP_COMMIT();   // always commit to keep group accounting fixed

        #pragma unroll
        for (int im = 0; im < 4; im++)
            #pragma unroll
            for (int in = 0; in < 8; in++)
                mma_f16(acc[im][in], af[im], bf[in >> 1][in & 1], bf[in >> 1][(in & 1) + 2]);

        // ks = 1 frags
        #pragma unroll
        for (int im = 0; im < 4; im++) ldsm4t(af[im], aA0[im] + aoff + 16 * APADH * 2);
        #pragma unroll
        for (int bg = 0; bg < 4; bg++) ldsm4(bf[bg], aB0[bg] + boff + 32);

        #pragma unroll
        for (int im = 0; im < 4; im++)
            #pragma unroll
            for (int in = 0; in < 8; in++)
                mma_f16(acc[im][in], af[im], bf[in >> 1][in & 1], bf[in >> 1][(in & 1) + 2]);
    }

    if (MODE == 0) {
        #pragma unroll
        for (int im = 0; im < 4; im++) {
            const int r_lo = wm + im * 16 + lq;
            const int r_hi = r_lo + 8;
            #pragma unroll
            for (int in = 0; in < 8; in++) {
                const int col = n0 + wn + in * 8 + lr * 2;
                const float b0 = bias[col], b1 = bias[col + 1];
                __half2 vlo = __floats2half2_rn(acc[im][in][0] + b0, acc[im][in][1] + b1);
                __half2 vhi = __floats2half2_rn(acc[im][in][2] + b0, acc[im][in][3] + b1);
                *(__half2*)(g_qkv_h + (size_t)(m0 + r_lo) * Nn + col) = vlo;
                *(__half2*)(g_qkv_h + (size_t)(m0 + r_hi) * Nn + col) = vhi;
            }
        }
    } else {
        __syncthreads();
        #pragma unroll
        for (int pass = 0; pass < 4; pass++) {
            #pragma unroll
            for (int im = 0; im < 4; im++) {
                #pragma unroll
                for (int inl = 0; inl < 2; inl++) {
                    const int in = pass * 2 + inl;
                    const int cp = inl * 8 + lr * 2;
                    stg[wid][cp][im * 16 + lq]         = acc[im][in][0];
                    stg[wid][cp + 1][im * 16 + lq]     = acc[im][in][1];
                    stg[wid][cp][im * 16 + lq + 8]     = acc[im][in][2];
                    stg[wid][cp + 1][im * 16 + lq + 8] = acc[im][in][3];
                }
            }
            __syncwarp();
            #pragma unroll
            for (int c = 0; c < 16; c++) {
                const int col = n0 + wn + pass * 16 + c;
                const float b = bias[col];
                size_t o = ((size_t)(t * CC + col)) * SS + s0 + wm + lane * 2;
                float2 v  = *(float2*)&stg[wid][c][lane * 2];
                float2 xr = *(const float2*)(x + o);
                *(float2*)(Cout + o) = make_float2(v.x + b + xr.x, v.y + b + xr.y);
            }
            __syncwarp();
        }
    }
}

// ---------------- 3) attention: one WARP per (head, s); 8 s per block ----------------
#define QSTRIDE 200
#define ATTN_SMEM (8 * 16 * QSTRIDE * 2)

__global__ __launch_bounds__(256)
void attn_kernel(const float* __restrict__ qs, const float* __restrict__ qb,
                 const float* __restrict__ ks, const float* __restrict__ kb,
                 const float* __restrict__ relb) {
    extern __shared__ __half sh[];
    const int head  = blockIdx.x;
    const int sbase = blockIdx.y * 8;
    const int tid   = threadIdx.x;
    const int w     = tid >> 5;
    const int lane  = tid & 31;
    const int s     = sbase + w;

    __half* Q = sh + w * 16 * QSTRIDE;

    {
        const __half* src = g_qkv_h + (size_t)s * NQKV + head * 192;
        #pragma unroll
        for (int m = lane; m < 384; m += 32) {
            int tt = m / 24, off = (m % 24) * 8;
            *(uint4*)(Q + tt * QSTRIDE + off) =
                *(const uint4*)(src + (size_t)tt * SS * NQKV + off);
        }
    }
    __syncwarp();

    {
        int r = lane & 15, which = lane >> 4;
        __half* p = Q + r * QSTRIDE + which * 64;
        float v[64];
        float sum = 0.f, ssq = 0.f;
        #pragma unroll
        for (int q8 = 0; q8 < 8; q8++) {
            uint4 u = *(uint4*)(p + q8 * 8);
            __half2* hp = (__half2*)&u;
            #pragma unroll
            for (int j = 0; j < 4; j++) {
                float2 f = __half22float2(hp[j]);
                v[q8 * 8 + j * 2]     = f.x;
                v[q8 * 8 + j * 2 + 1] = f.y;
                sum += f.x + f.y;
                ssq += f.x * f.x + f.y * f.y;
            }
        }
        float mu  = sum * (1.0f / 64.0f);
        float var = ssq * (1.0f / 64.0f) - mu * mu;
        float inv = rsqrtf(var + 1e-6f);
        const float* sc = which ? ks : qs;
        const float* bi = which ? kb : qb;
        #pragma unroll
        for (int q8 = 0; q8 < 8; q8++) {
            uint32_t o[4];
            #pragma unroll
            for (int j = 0; j < 4; j++) {
                int c = q8 * 8 + j * 2;
                o[j] = packh((v[c] - mu) * inv * sc[c] + bi[c],
                             (v[c + 1] - mu) * inv * sc[c + 1] + bi[c + 1]);
            }
            *(uint4*)(p + q8 * 8) = *(uint4*)o;
        }
    }
    __syncwarp();

    const int i  = lane >> 1;
    const int j0 = (lane & 1) * 8;
    float wgt[8];
    {
        float qv[64];
        const __half* qp = Q + i * QSTRIDE;
        #pragma unroll
        for (int q8 = 0; q8 < 8; q8++) {
            uint4 u = *(const uint4*)(qp + q8 * 8);
            __half2* hp = (__half2*)&u;
            #pragma unroll
            for (int j = 0; j < 4; j++) {
                float2 f = __half22float2(hp[j]);
                qv[q8 * 8 + j * 2] = f.x; qv[q8 * 8 + j * 2 + 1] = f.y;
            }
        }
        float scv[8];
        #pragma unroll
        for (int jj = 0; jj < 8; jj++) {
            int j = j0 + jj;
            const __half* kp = Q + j * QSTRIDE + 64;
            float dot = 0.f;
            #pragma unroll
            for (int q8 = 0; q8 < 8; q8++) {
                uint4 u = *(const uint4*)(kp + q8 * 8);
                __half2* hp = (__half2*)&u;
                #pragma unroll
                for (int c = 0; c < 4; c++) {
                    float2 f = __half22float2(hp[c]);
                    dot += qv[q8 * 8 + c * 2] * f.x + qv[q8 * 8 + c * 2 + 1] * f.y;
                }
            }
            int rp = j - i;
            int bucket = (rp > 0) ? 16 : 0;
            int n = abs(rp);
            if (n < 8) bucket += n;
            else {
                int large = 8 + (int)(__logf((float)n * 0.125f) * (8.0f / 2.7725887222397811f));
                bucket += (large < 15) ? large : 15;
            }
            scv[jj] = dot * 0.125f + relb[bucket * NHEAD + head];
        }
        float mx = scv[0];
        #pragma unroll
        for (int jj = 1; jj < 8; jj++) mx = fmaxf(mx, scv[jj]);
        mx = fmaxf(mx, __shfl_xor_sync(0xffffffffu, mx, 1));
        float sm = 0.f;
        #pragma unroll
        for (int jj = 0; jj < 8; jj++) { wgt[jj] = __expf(scv[jj] - mx); sm += wgt[jj]; }
        sm += __shfl_xor_sync(0xffffffffu, sm, 1);
        float r = 1.0f / sm;
        #pragma unroll
        for (int jj = 0; jj < 8; jj++) wgt[jj] *= r;
    }

    {
        float outp[64];
        #pragma unroll
        for (int c = 0; c < 64; c++) outp[c] = 0.f;
        #pragma unroll
        for (int u = 0; u < 8; u++) {
            const __half* vp = Q + (j0 + u) * QSTRIDE + 128;
            float wv = wgt[u];
            #pragma unroll
            for (int q8 = 0; q8 < 8; q8++) {
                uint4 uu = *(const uint4*)(vp + q8 * 8);
                __half2* hp = (__half2*)&uu;
                #pragma unroll
                for (int c = 0; c < 4; c++) {
                    float2 f = __half22float2(hp[c]);
                    outp[q8 * 8 + c * 2]     += wv * f.x;
                    outp[q8 * 8 + c * 2 + 1] += wv * f.y;
                }
            }
        }
        #pragma unroll
        for (int c = 0; c < 64; c++)
            outp[c] += __shfl_xor_sync(0xffffffffu, outp[c], 1);
        if (!(lane & 1)) {
            #pragma unroll
            for (int q8 = 0; q8 < 8; q8++) {
                uint32_t o[4];
                #pragma unroll
                for (int j = 0; j < 4; j++)
                    o[j] = packh(outp[q8 * 8 + j * 2], outp[q8 * 8 + j * 2 + 1]);
                *(uint4*)(Q + i * QSTRIDE + q8 * 8) = *(uint4*)o;
            }
        }
    }
    __syncthreads();

    for (int idx = tid; idx < 16 * 64; idx += 256) {
        int t_ = idx >> 6;
        int c  = idx & 63;
        __half h[8];
        #pragma unroll
        for (int w2 = 0; w2 < 8; w2++)
            h[w2] = sh[w2 * 16 * QSTRIDE + t_ * QSTRIDE + c];
        *(uint4*)(g_att_h + ((size_t)(t_ * CC + head * 64 + c)) * SS + sbase) = *(uint4*)h;
    }
}

extern "C" void kernel_launch(void* const* d_in, const int* in_sizes, int n_in,
                              void* d_out, int out_size) {
    const float* x    = (const float*)d_in[0];
    const float* w1   = (const float*)d_in[1];
    const float* Win  = (const float*)d_in[2];
    const float* binq = (const float*)d_in[3];
    const float* qsc  = (const float*)d_in[4];
    const float* qbi  = (const float*)d_in[5];
    const float* ksc  = (const float*)d_in[6];
    const float* kbi  = (const float*)d_in[7];
    const float* relb = (const float*)d_in[8];
    const float* Wout = (const float*)d_in[9];
    const float* bout = (const float*)d_in[10];
    float* out = (float*)d_out;

    __half *wh_in_p, *wh_out_p;
    cudaGetSymbolAddress((void**)&wh_in_p, g_wh_in);
    cudaGetSymbolAddress((void**)&wh_out_p, g_wh_out);
    cudaFuncSetAttribute(attn_kernel, cudaFuncAttributeMaxDynamicSharedMemorySize, ATTN_SMEM);
    cudaFuncSetAttribute(mma_gemm<0>, cudaFuncAttributeMaxDynamicSharedMemorySize, GEMM_SMEM);
    cudaFuncSetAttribute(mma_gemm<1>, cudaFuncAttributeMaxDynamicSharedMemorySize, GEMM_SMEM);

    rms_conv_kernel<<<TT * NHEAD, 256>>>(x, w1);
    convw_kernel<<<(NQKV * CC / 4 + 255) / 256, 256>>>(Win, wh_in_p, NQKV * CC / 4);
    convw_kernel<<<(CC * CC / 4 + 255) / 256, 256>>>(Wout, wh_out_p, CC * CC / 4);
    mma_gemm<0><<<dim3(NQKV / 128, 32768 / 256), 256, GEMM_SMEM>>>(x, binq, nullptr, NQKV);
    attn_kernel<<<dim3(NHEAD, SS / 8), 256, ATTN_SMEM>>>(qsc, qbi, ksc, kbi, relb);
    mma_gemm<1><<<dim3(CC / 128, 32768 / 256), 256, GEMM_SMEM>>>(x, bout, out, CC);
}

// round 15
// speedup vs baseline: 1.0318x; 1.0318x over previous
#include <cuda_runtime.h>
#include <cuda_fp16.h>
#include <cstdint>

#define TT 16
#define CC 768
#define SS 2048
#define NHEAD 12
#define HDIM 64
#define NQKV 2304

// Scratch (device globals; no allocation allowed)
__device__ __half g_xh[(size_t)TT * CC * SS];          // fp16(x * invrms * w1), [t][k][s]
__device__ __half g_wh_in[(size_t)NQKV * CC];          // fp16(Win)
__device__ __half g_wh_out[(size_t)CC * CC];           // fp16(Wout)
__device__ __half g_qkv_h[(size_t)32768 * NQKV];       // [m=t*2048+s][n] fp16
__device__ __half g_att_h[(size_t)TT * CC * SS];       // [t][c][s] fp16

__device__ __forceinline__ uint32_t packh(float lo, float hi) {
    __half2 h = __floats2half2_rn(lo, hi);
    return *(uint32_t*)&h;
}

__device__ __forceinline__ void mma_f16(float* d, const uint32_t* a, uint32_t b0, uint32_t b1) {
    asm volatile(
        "mma.sync.aligned.m16n8k16.row.col.f32.f16.f16.f32 "
        "{%0,%1,%2,%3}, {%4,%5,%6,%7}, {%8,%9}, {%0,%1,%2,%3};"
        : "+f"(d[0]), "+f"(d[1]), "+f"(d[2]), "+f"(d[3])
        : "r"(a[0]), "r"(a[1]), "r"(a[2]), "r"(a[3]), "r"(b0), "r"(b1));
}

__device__ __forceinline__ void cp16(uint32_t dst, const void* src) {
    asm volatile("cp.async.cg.shared.global [%0], [%1], 16;" :: "r"(dst), "l"(src));
}
#define CP_COMMIT() asm volatile("cp.async.commit_group;" ::: "memory")
#define CP_WAIT1()  asm volatile("cp.async.wait_group 1;" ::: "memory")

__device__ __forceinline__ void ldsm4(uint32_t* r, uint32_t addr) {
    asm volatile("ldmatrix.sync.aligned.m8n8.x4.shared.b16 {%0,%1,%2,%3}, [%4];"
        : "=r"(r[0]), "=r"(r[1]), "=r"(r[2]), "=r"(r[3]) : "r"(addr));
}
__device__ __forceinline__ void ldsm4t(uint32_t* r, uint32_t addr) {
    asm volatile("ldmatrix.sync.aligned.m8n8.x4.trans.shared.b16 {%0,%1,%2,%3}, [%4];"
        : "=r"(r[0]), "=r"(r[1]), "=r"(r[2]), "=r"(r[3]) : "r"(addr));
}

// ---------------- 1) group RMS + fp16 conversion (fused) ----------------
__global__ __launch_bounds__(256)
void rms_conv_kernel(const float* __restrict__ x, const float* __restrict__ w1) {
    int b = blockIdx.x;
    int t = b / NHEAD, g = b - t * NHEAD;
    const float4* p = (const float4*)(x + (size_t)b * 64 * SS);
    float s = 0.f;
    for (int i = threadIdx.x; i < (64 * SS) / 4; i += 256) {
        float4 v = p[i];
        s += v.x * v.x + v.y * v.y + v.z * v.z + v.w * v.w;
    }
    #pragma unroll
    for (int m = 16; m; m >>= 1) s += __shfl_xor_sync(0xffffffffu, s, m);
    __shared__ float red[8];
    __shared__ float s_inv;
    if ((threadIdx.x & 31) == 0) red[threadIdx.x >> 5] = s;
    __syncthreads();
    if (threadIdx.x == 0) {
        float tot = 0.f;
        #pragma unroll
        for (int j = 0; j < 8; j++) tot += red[j];
        s_inv = rsqrtf(tot * (1.0f / (64.0f * SS)) + 1e-6f);
    }
    __syncthreads();
    const float inv = s_inv;

    for (int i = threadIdx.x; i < (64 * SS) / 8; i += 256) {
        int row = i >> 8;
        int off = (i & 255) * 8;
        float sc = inv * w1[g * 64 + row];
        const float4* src = (const float4*)(x + ((size_t)b * 64 + row) * SS + off);
        float4 a = src[0], c = src[1];
        uint32_t o[4] = {packh(a.x * sc, a.y * sc), packh(a.z * sc, a.w * sc),
                         packh(c.x * sc, c.y * sc), packh(c.z * sc, c.w * sc)};
        *(uint4*)(g_xh + ((size_t)(t * CC + g * 64 + row)) * SS + off) = *(uint4*)o;
    }
}

// ---------------- 1c) prep: fp16 weight copies ----------------
__global__ __launch_bounds__(256)
void convw_kernel(const float* __restrict__ src, __half* __restrict__ dst, int n4) {
    int i = blockIdx.x * blockDim.x + threadIdx.x;
    if (i < n4) {
        float4 v = ((const float4*)src)[i];
        uint32_t o[2] = {packh(v.x, v.y), packh(v.z, v.w)};
        *(uint2*)(dst + (size_t)i * 4) = *(uint2*)o;
    }
}

// ---------------- 2/4) mma.sync fp16 GEMM, CTA 128x128, K-chunk 64, 3-stage ----------------
// 8 warps (2 m x 4 n), warp tile 64x32, 2 CTAs/SM.
// As[k][m]: 64 x 136 halves/stage (stride 272B — ldsm4t conflict-free).
// Bs[n][k]: 128 x 72 halves/stage (stride 144B — ldsm4 conflict-free).
#define NKIT3 12
#define APADH 136
#define ASTG_BYTES (64 * APADH * 2)         // 17408
#define BPADH 72
#define BSTG_BYTES (128 * BPADH * 2)        // 18432
#define GEMM_SMEM (3 * (ASTG_BYTES + BSTG_BYTES))   // 107520

template <int MODE>
__global__ __launch_bounds__(256, 2)
void mma_gemm(const float* __restrict__ x, const float* __restrict__ bias,
              float* __restrict__ Cout, int Nn) {
    extern __shared__ __align__(16) char smem_raw[];
    __half (*As)[64][APADH]  = (__half (*)[64][APADH])smem_raw;
    __half (*Bs)[128][BPADH] = (__half (*)[128][BPADH])(smem_raw + 3 * ASTG_BYTES);
    float (*stg)[16][68]     = (float (*)[16][68])smem_raw;   // MODE 1 epilogue overlay

    const int tid  = threadIdx.x;
    const int wid  = tid >> 5;
    const int lane = tid & 31;
    const int wm   = (wid & 1) * 64;
    const int wn   = (wid >> 1) * 32;
    const int lq   = lane >> 2;
    const int lr   = lane & 3;

    const int m0 = blockIdx.y * 128;
    const int n0 = blockIdx.x * 128;
    const int t  = m0 >> 11;
    const int s0 = m0 & 2047;

    const __half* Asrc = (MODE == 0) ? g_xh : g_att_h;
    const __half* Bsrc = (MODE == 0) ? g_wh_in : g_wh_out;

    // ldmatrix lane base addresses (stage 0)
    const int kA_l = ((lane >> 4) << 3) + (lane & 7);
    const int mOff = (((lane >> 3) & 1) << 3);
    const int nB_l = (((lane >> 3) & 1) << 3) + (lane & 7);
    const int kB_l = ((lane >> 4) << 3);
    uint32_t aA0[4], aB0[2];
    #pragma unroll
    for (int im = 0; im < 4; im++)
        aA0[im] = (uint32_t)__cvta_generic_to_shared(&As[0][kA_l][wm + im * 16 + mOff]);
    #pragma unroll
    for (int bg = 0; bg < 2; bg++)
        aB0[bg] = (uint32_t)__cvta_generic_to_shared(&Bs[0][wn + bg * 16 + nB_l][kB_l]);

    float acc[4][4][4];
    #pragma unroll
    for (int i = 0; i < 4; i++)
        #pragma unroll
        for (int j = 0; j < 4; j++)
            #pragma unroll
            for (int c = 0; c < 4; c++) acc[i][j][c] = 0.f;

    auto issueA = [&](int k0, int p) {   // 64 rows x 128 halves = 1024 chunks, 4/thread
        #pragma unroll
        for (int r = 0; r < 4; r++) {
            int o = tid * 4 + r;
            int row = o >> 4;            // 0..63
            int ch  = (o & 15) * 8;
            cp16((uint32_t)__cvta_generic_to_shared(&As[p][row][ch]),
                 Asrc + ((size_t)(t * CC + k0 + row)) * SS + s0 + ch);
        }
    };
    auto issueB = [&](int k0, int p) {   // 128 rows x 64 halves = 1024 chunks, 4/thread
        #pragma unroll
        for (int r = 0; r < 4; r++) {
            int o = tid * 4 + r;
            int row = o >> 3;            // 0..127
            int ch  = (o & 7) * 8;       // 0..56
            cp16((uint32_t)__cvta_generic_to_shared(&Bs[p][row][ch]),
                 Bsrc + (size_t)(n0 + row) * CC + k0 + ch);
        }
    };

    // prologue: stages 0,1 as groups g0,g1
    #pragma unroll
    for (int p = 0; p < 2; p++) {
        issueA(p * 64, p);
        issueB(p * 64, p);
        CP_COMMIT();
    }

    for (int i = 0; i < NKIT3; i++) {
        const int p = i % 3;
        CP_WAIT1();
        __syncthreads();

        const uint32_t aoff = (uint32_t)(p * ASTG_BYTES);
        const uint32_t boff = (uint32_t)(p * BSTG_BYTES);

        uint32_t af[2][4][4], bf[2][2][4];
        // frags for ks 0,1
        #pragma unroll
        for (int ksl = 0; ksl < 2; ksl++) {
            #pragma unroll
            for (int im = 0; im < 4; im++)
                ldsm4t(af[ksl][im], aA0[im] + aoff + ksl * (16 * APADH * 2));
            #pragma unroll
            for (int bg = 0; bg < 2; bg++)
                ldsm4(bf[ksl][bg], aB0[bg] + boff + ksl * 32);
        }

        if (i + 2 < NKIT3) {
            const int pn = (i + 2) % 3;
            issueA((i + 2) * 64, pn);
            issueB((i + 2) * 64, pn);
        }
        CP_COMMIT();   // always commit to keep group accounting fixed

        #pragma unroll
        for (int ksl = 0; ksl < 2; ksl++)
            #pragma unroll
            for (int im = 0; im < 4; im++)
                #pragma unroll
                for (int in = 0; in < 4; in++)
                    mma_f16(acc[im][in], af[ksl][im],
                            bf[ksl][in >> 1][in & 1], bf[ksl][in >> 1][(in & 1) + 2]);

        // frags for ks 2,3
        #pragma unroll
        for (int ksl = 0; ksl < 2; ksl++) {
            #pragma unroll
            for (int im = 0; im < 4; im++)
                ldsm4t(af[ksl][im], aA0[im] + aoff + (ksl + 2) * (16 * APADH * 2));
            #pragma unroll
            for (int bg = 0; bg < 2; bg++)
                ldsm4(bf[ksl][bg], aB0[bg] + boff + (ksl + 2) * 32);
        }

        #pragma unroll
        for (int ksl = 0; ksl < 2; ksl++)
            #pragma unroll
            for (int im = 0; im < 4; im++)
                #pragma unroll
                for (int in = 0; in < 4; in++)
                    mma_f16(acc[im][in], af[ksl][im],
                            bf[ksl][in >> 1][in & 1], bf[ksl][in >> 1][(in & 1) + 2]);
    }

    if (MODE == 0) {
        #pragma unroll
        for (int im = 0; im < 4; im++) {
            const int r_lo = wm + im * 16 + lq;
            const int r_hi = r_lo + 8;
            #pragma unroll
            for (int in = 0; in < 4; in++) {
                const int col = n0 + wn + in * 8 + lr * 2;
                const float b0 = bias[col], b1 = bias[col + 1];
                __half2 vlo = __floats2half2_rn(acc[im][in][0] + b0, acc[im][in][1] + b1);
                __half2 vhi = __floats2half2_rn(acc[im][in][2] + b0, acc[im][in][3] + b1);
                *(__half2*)(g_qkv_h + (size_t)(m0 + r_lo) * Nn + col) = vlo;
                *(__half2*)(g_qkv_h + (size_t)(m0 + r_hi) * Nn + col) = vhi;
            }
        }
    } else {
        __syncthreads();
        #pragma unroll
        for (int pass = 0; pass < 2; pass++) {
            #pragma unroll
            for (int im = 0; im < 4; im++) {
                #pragma unroll
                for (int inl = 0; inl < 2; inl++) {
                    const int in = pass * 2 + inl;
                    const int cp = inl * 8 + lr * 2;
                    stg[wid][cp][im * 16 + lq]         = acc[im][in][0];
                    stg[wid][cp + 1][im * 16 + lq]     = acc[im][in][1];
                    stg[wid][cp][im * 16 + lq + 8]     = acc[im][in][2];
                    stg[wid][cp + 1][im * 16 + lq + 8] = acc[im][in][3];
                }
            }
            __syncwarp();
            #pragma unroll
            for (int c = 0; c < 16; c++) {
                const int col = n0 + wn + pass * 16 + c;
                const float b = bias[col];
                size_t o = ((size_t)(t * CC + col)) * SS + s0 + wm + lane * 2;
                float2 v  = *(float2*)&stg[wid][c][lane * 2];
                float2 xr = *(const float2*)(x + o);
                *(float2*)(Cout + o) = make_float2(v.x + b + xr.x, v.y + b + xr.y);
            }
            __syncwarp();
        }
    }
}

// ---------------- 3) attention: one WARP per (head, s); 8 s per block ----------------
#define QSTRIDE 200
#define ATTN_SMEM (8 * 16 * QSTRIDE * 2)

__global__ __launch_bounds__(256)
void attn_kernel(const float* __restrict__ qs, const float* __restrict__ qb,
                 const float* __restrict__ ks, const float* __restrict__ kb,
                 const float* __restrict__ relb) {
    extern __shared__ __half sh[];
    const int head  = blockIdx.x;
    const int sbase = blockIdx.y * 8;
    const int tid   = threadIdx.x;
    const int w     = tid >> 5;
    const int lane  = tid & 31;
    const int s     = sbase + w;

    __half* Q = sh + w * 16 * QSTRIDE;

    {
        const __half* src = g_qkv_h + (size_t)s * NQKV + head * 192;
        #pragma unroll
        for (int m = lane; m < 384; m += 32) {
            int tt = m / 24, off = (m % 24) * 8;
            *(uint4*)(Q + tt * QSTRIDE + off) =
                *(const uint4*)(src + (size_t)tt * SS * NQKV + off);
        }
    }
    __syncwarp();

    {
        int r = lane & 15, which = lane >> 4;
        __half* p = Q + r * QSTRIDE + which * 64;
        float v[64];
        float sum = 0.f, ssq = 0.f;
        #pragma unroll
        for (int q8 = 0; q8 < 8; q8++) {
            uint4 u = *(uint4*)(p + q8 * 8);
            __half2* hp = (__half2*)&u;
            #pragma unroll
            for (int j = 0; j < 4; j++) {
                float2 f = __half22float2(hp[j]);
                v[q8 * 8 + j * 2]     = f.x;
                v[q8 * 8 + j * 2 + 1] = f.y;
                sum += f.x + f.y;
                ssq += f.x * f.x + f.y * f.y;
            }
        }
        float mu  = sum * (1.0f / 64.0f);
        float var = ssq * (1.0f / 64.0f) - mu * mu;
        float inv = rsqrtf(var + 1e-6f);
        const float* sc = which ? ks : qs;
        const float* bi = which ? kb : qb;
        #pragma unroll
        for (int q8 = 0; q8 < 8; q8++) {
            uint32_t o[4];
            #pragma unroll
            for (int j = 0; j < 4; j++) {
                int c = q8 * 8 + j * 2;
                o[j] = packh((v[c] - mu) * inv * sc[c] + bi[c],
                             (v[c + 1] - mu) * inv * sc[c + 1] + bi[c + 1]);
            }
            *(uint4*)(p + q8 * 8) = *(uint4*)o;
        }
    }
    __syncwarp();

    const int i  = lane >> 1;
    const int j0 = (lane & 1) * 8;
    float wgt[8];
    {
        float qv[64];
        const __half* qp = Q + i * QSTRIDE;
        #pragma unroll
        for (int q8 = 0; q8 < 8; q8++) {
            uint4 u = *(const uint4*)(qp + q8 * 8);
            __half2* hp = (__half2*)&u;
            #pragma unroll
            for (int j = 0; j < 4; j++) {
                float2 f = __half22float2(hp[j]);
                qv[q8 * 8 + j * 2] = f.x; qv[q8 * 8 + j * 2 + 1] = f.y;
            }
        }
        float scv[8];
        #pragma unroll
        for (int jj = 0; jj < 8; jj++) {
            int j = j0 + jj;
            const __half* kp = Q + j * QSTRIDE + 64;
            float dot = 0.f;
            #pragma unroll
            for (int q8 = 0; q8 < 8; q8++) {
                uint4 u = *(const uint4*)(kp + q8 * 8);
                __half2* hp = (__half2*)&u;
                #pragma unroll
                for (int c = 0; c < 4; c++) {
                    float2 f = __half22float2(hp[c]);
                    dot += qv[q8 * 8 + c * 2] * f.x + qv[q8 * 8 + c * 2 + 1] * f.y;
                }
            }
            int rp = j - i;
            int bucket = (rp > 0) ? 16 : 0;
            int n = abs(rp);
            if (n < 8) bucket += n;
            else {
                int large = 8 + (int)(__logf((float)n * 0.125f) * (8.0f / 2.7725887222397811f));
                bucket += (large < 15) ? large : 15;
            }
            scv[jj] = dot * 0.125f + relb[bucket * NHEAD + head];
        }
        float mx = scv[0];
        #pragma unroll
        for (int jj = 1; jj < 8; jj++) mx = fmaxf(mx, scv[jj]);
        mx = fmaxf(mx, __shfl_xor_sync(0xffffffffu, mx, 1));
        float sm = 0.f;
        #pragma unroll
        for (int jj = 0; jj < 8; jj++) { wgt[jj] = __expf(scv[jj] - mx); sm += wgt[jj]; }
        sm += __shfl_xor_sync(0xffffffffu, sm, 1);
        float r = 1.0f / sm;
        #pragma unroll
        for (int jj = 0; jj < 8; jj++) wgt[jj] *= r;
    }

    {
        float outp[64];
        #pragma unroll
        for (int c = 0; c < 64; c++) outp[c] = 0.f;
        #pragma unroll
        for (int u = 0; u < 8; u++) {
            const __half* vp = Q + (j0 + u) * QSTRIDE + 128;
            float wv = wgt[u];
            #pragma unroll
            for (int q8 = 0; q8 < 8; q8++) {
                uint4 uu = *(const uint4*)(vp + q8 * 8);
                __half2* hp = (__half2*)&uu;
                #pragma unroll
                for (int c = 0; c < 4; c++) {
                    float2 f = __half22float2(hp[c]);
                    outp[q8 * 8 + c * 2]     += wv * f.x;
                    outp[q8 * 8 + c * 2 + 1] += wv * f.y;
                }
            }
        }
        #pragma unroll
        for (int c = 0; c < 64; c++)
            outp[c] += __shfl_xor_sync(0xffffffffu, outp[c], 1);
        if (!(lane & 1)) {
            #pragma unroll
            for (int q8 = 0; q8 < 8; q8++) {
                uint32_t o[4];
                #pragma unroll
                for (int j = 0; j < 4; j++)
                    o[j] = packh(outp[q8 * 8 + j * 2], outp[q8 * 8 + j * 2 + 1]);
                *(uint4*)(Q + i * QSTRIDE + q8 * 8) = *(uint4*)o;
            }
        }
    }
    __syncthreads();

    for (int idx = tid; idx < 16 * 64; idx += 256) {
        int t_ = idx >> 6;
        int c  = idx & 63;
        __half h[8];
        #pragma unroll
        for (int w2 = 0; w2 < 8; w2++)
            h[w2] = sh[w2 * 16 * QSTRIDE + t_ * QSTRIDE + c];
        *(uint4*)(g_att_h + ((size_t)(t_ * CC + head * 64 + c)) * SS + sbase) = *(uint4*)h;
    }
}

extern "C" void kernel_launch(void* const* d_in, const int* in_sizes, int n_in,
                              void* d_out, int out_size) {
    const float* x    = (const float*)d_in[0];
    const float* w1   = (const float*)d_in[1];
    const float* Win  = (const float*)d_in[2];
    const float* binq = (const float*)d_in[3];
    const float* qsc  = (const float*)d_in[4];
    const float* qbi  = (const float*)d_in[5];
    const float* ksc  = (const float*)d_in[6];
    const float* kbi  = (const float*)d_in[7];
    const float* relb = (const float*)d_in[8];
    const float* Wout = (const float*)d_in[9];
    const float* bout = (const float*)d_in[10];
    float* out = (float*)d_out;

    __half *wh_in_p, *wh_out_p;
    cudaGetSymbolAddress((void**)&wh_in_p, g_wh_in);
    cudaGetSymbolAddress((void**)&wh_out_p, g_wh_out);
    cudaFuncSetAttribute(attn_kernel, cudaFuncAttributeMaxDynamicSharedMemorySize, ATTN_SMEM);
    cudaFuncSetAttribute(mma_gemm<0>, cudaFuncAttributeMaxDynamicSharedMemorySize, GEMM_SMEM);
    cudaFuncSetAttribute(mma_gemm<1>, cudaFuncAttributeMaxDynamicSharedMemorySize, GEMM_SMEM);

    rms_conv_kernel<<<TT * NHEAD, 256>>>(x, w1);
    convw_kernel<<<(NQKV * CC / 4 + 255) / 256, 256>>>(Win, wh_in_p, NQKV * CC / 4);
    convw_kernel<<<(CC * CC / 4 + 255) / 256, 256>>>(Wout, wh_out_p, CC * CC / 4);
    mma_gemm<0><<<dim3(NQKV / 128, 32768 / 128), 256, GEMM_SMEM>>>(x, binq, nullptr, NQKV);
    attn_kernel<<<dim3(NHEAD, SS / 8), 256, ATTN_SMEM>>>(qsc, qbi, ksc, kbi, relb);
    mma_gemm<1><<<dim3(CC / 128, 32768 / 128), 256, GEMM_SMEM>>>(x, bout, out, CC);
}

// round 16
// speedup vs baseline: 1.1530x; 1.1175x over previous
#include <cuda_runtime.h>
#include <cuda_fp16.h>
#include <cstdint>

#define TT 16
#define CC 768
#define SS 2048
#define NHEAD 12
#define HDIM 64
#define NQKV 2304

// Scratch (device globals; no allocation allowed)
__device__ __half g_xh[(size_t)TT * CC * SS];          // fp16(x * invrms * w1), [t][k][s]
__device__ __half g_wh_in[(size_t)NQKV * CC];          // fp16(Win)
__device__ __half g_wh_out[(size_t)CC * CC];           // fp16(Wout)
__device__ __half g_qkv_h[(size_t)32768 * NQKV];       // [m=t*2048+s][n] fp16
__device__ __half g_att_h[(size_t)TT * CC * SS];       // [t][c][s] fp16

__device__ __forceinline__ uint32_t packh(float lo, float hi) {
    __half2 h = __floats2half2_rn(lo, hi);
    return *(uint32_t*)&h;
}

__device__ __forceinline__ void mma_f16(float* d, const uint32_t* a, uint32_t b0, uint32_t b1) {
    asm volatile(
        "mma.sync.aligned.m16n8k16.row.col.f32.f16.f16.f32 "
        "{%0,%1,%2,%3}, {%4,%5,%6,%7}, {%8,%9}, {%0,%1,%2,%3};"
        : "+f"(d[0]), "+f"(d[1]), "+f"(d[2]), "+f"(d[3])
        : "r"(a[0]), "r"(a[1]), "r"(a[2]), "r"(a[3]), "r"(b0), "r"(b1));
}

__device__ __forceinline__ void cp16(uint32_t dst, const void* src) {
    asm volatile("cp.async.cg.shared.global [%0], [%1], 16;" :: "r"(dst), "l"(src));
}
#define CP_COMMIT() asm volatile("cp.async.commit_group;" ::: "memory")
#define CP_WAIT3()  asm volatile("cp.async.wait_group 3;" ::: "memory")

__device__ __forceinline__ void ldsm4(uint32_t* r, uint32_t addr) {
    asm volatile("ldmatrix.sync.aligned.m8n8.x4.shared.b16 {%0,%1,%2,%3}, [%4];"
        : "=r"(r[0]), "=r"(r[1]), "=r"(r[2]), "=r"(r[3]) : "r"(addr));
}
__device__ __forceinline__ void ldsm4t(uint32_t* r, uint32_t addr) {
    asm volatile("ldmatrix.sync.aligned.m8n8.x4.trans.shared.b16 {%0,%1,%2,%3}, [%4];"
        : "=r"(r[0]), "=r"(r[1]), "=r"(r[2]), "=r"(r[3]) : "r"(addr));
}

// ---------------- 1) group RMS + fp16 conversion (fused) ----------------
__global__ __launch_bounds__(256)
void rms_conv_kernel(const float* __restrict__ x, const float* __restrict__ w1) {
    int b = blockIdx.x;
    int t = b / NHEAD, g = b - t * NHEAD;
    const float4* p = (const float4*)(x + (size_t)b * 64 * SS);
    float s = 0.f;
    for (int i = threadIdx.x; i < (64 * SS) / 4; i += 256) {
        float4 v = p[i];
        s += v.x * v.x + v.y * v.y + v.z * v.z + v.w * v.w;
    }
    #pragma unroll
    for (int m = 16; m; m >>= 1) s += __shfl_xor_sync(0xffffffffu, s, m);
    __shared__ float red[8];
    __shared__ float s_inv;
    if ((threadIdx.x & 31) == 0) red[threadIdx.x >> 5] = s;
    __syncthreads();
    if (threadIdx.x == 0) {
        float tot = 0.f;
        #pragma unroll
        for (int j = 0; j < 8; j++) tot += red[j];
        s_inv = rsqrtf(tot * (1.0f / (64.0f * SS)) + 1e-6f);
    }
    __syncthreads();
    const float inv = s_inv;

    for (int i = threadIdx.x; i < (64 * SS) / 8; i += 256) {
        int row = i >> 8;
        int off = (i & 255) * 8;
        float sc = inv * w1[g * 64 + row];
        const float4* src = (const float4*)(x + ((size_t)b * 64 + row) * SS + off);
        float4 a = src[0], c = src[1];
        uint32_t o[4] = {packh(a.x * sc, a.y * sc), packh(a.z * sc, a.w * sc),
                         packh(c.x * sc, c.y * sc), packh(c.z * sc, c.w * sc)};
        *(uint4*)(g_xh + ((size_t)(t * CC + g * 64 + row)) * SS + off) = *(uint4*)o;
    }
}

// ---------------- 1c) prep: both fp16 weight copies in one launch ----------------
#define N4_IN  (NQKV * CC / 4)
#define N4_OUT (CC * CC / 4)
__global__ __launch_bounds__(256)
void convw_kernel(const float* __restrict__ srcA, __half* __restrict__ dstA,
                  const float* __restrict__ srcB, __half* __restrict__ dstB) {
    int i = blockIdx.x * blockDim.x + threadIdx.x;
    const float* src;
    __half* dst;
    int j;
    if (i < N4_IN) { src = srcA; dst = dstA; j = i; }
    else if (i < N4_IN + N4_OUT) { src = srcB; dst = dstB; j = i - N4_IN; }
    else return;
    float4 v = ((const float4*)src)[j];
    uint32_t o[2] = {packh(v.x, v.y), packh(v.z, v.w)};
    *(uint2*)(dst + (size_t)j * 4) = *(uint2*)o;
}

// ---------------- 2/4) mma.sync fp16 GEMM, 5-stage cp.async ----------------
#define NKIT2 24
#define APADH 136
#define BPADH 40
#define ASTG_BYTES (32 * APADH * 2)         // 8704
#define BSTG_BYTES (128 * BPADH * 2)        // 10240
#define NSTG 5
#define GEMM_SMEM (NSTG * (ASTG_BYTES + BSTG_BYTES))   // 94720

template <int MODE>
__global__ __launch_bounds__(256, 2)
void mma_gemm(const float* __restrict__ x, const float* __restrict__ bias,
              float* __restrict__ Cout, int Nn) {
    extern __shared__ __align__(16) char smem_raw[];
    __half (*As)[32][APADH]  = (__half (*)[32][APADH])smem_raw;
    __half (*Bs)[128][BPADH] = (__half (*)[128][BPADH])(smem_raw + NSTG * ASTG_BYTES);
    float (*stg)[16][68]     = (float (*)[16][68])smem_raw;   // MODE 1 epilogue overlay

    const int tid  = threadIdx.x;
    const int wid  = tid >> 5;
    const int lane = tid & 31;
    const int wm   = (wid & 1) * 64;
    const int wn   = (wid >> 1) * 32;
    const int lq   = lane >> 2;
    const int lr   = lane & 3;

    const int m0 = blockIdx.y * 128;
    const int n0 = blockIdx.x * 128;
    const int t  = m0 >> 11;
    const int s0 = m0 & 2047;

    const __half* Asrc = (MODE == 0) ? g_xh : g_att_h;
    const __half* Bsrc = (MODE == 0) ? g_wh_in : g_wh_out;

    // ldmatrix lane base addresses (stage 0)
    const int kA_l = ((lane >> 4) << 3) + (lane & 7);
    const int mOff = (((lane >> 3) & 1) << 3);
    const int nB_l = (((lane >> 3) & 1) << 3) + (lane & 7);
    const int kB_l = ((lane >> 4) << 3);
    uint32_t aA0[4], aB0[2];
    #pragma unroll
    for (int im = 0; im < 4; im++)
        aA0[im] = (uint32_t)__cvta_generic_to_shared(&As[0][kA_l][wm + im * 16 + mOff]);
    #pragma unroll
    for (int bg = 0; bg < 2; bg++)
        aB0[bg] = (uint32_t)__cvta_generic_to_shared(&Bs[0][wn + bg * 16 + nB_l][kB_l]);

    float acc[4][4][4];
    #pragma unroll
    for (int i = 0; i < 4; i++)
        #pragma unroll
        for (int j = 0; j < 4; j++)
            #pragma unroll
            for (int c = 0; c < 4; c++) acc[i][j][c] = 0.f;

    auto issueA = [&](int k0, int p) {
        #pragma unroll
        for (int r = 0; r < 2; r++) {
            int o = tid * 2 + r;
            int row = o >> 4;
            int ch  = (o & 15) * 8;
            cp16((uint32_t)__cvta_generic_to_shared(&As[p][row][ch]),
                 Asrc + ((size_t)(t * CC + k0 + row)) * SS + s0 + ch);
        }
    };
    auto issueB = [&](int k0, int p) {
        #pragma unroll
        for (int r = 0; r < 2; r++) {
            int o = tid * 2 + r;
            int row = o >> 2;
            int ch  = (o & 3) * 8;
            cp16((uint32_t)__cvta_generic_to_shared(&Bs[p][row][ch]),
                 Bsrc + (size_t)(n0 + row) * CC + k0 + ch);
        }
    };

    // prologue: stages 0..3 as groups g0..g3
    #pragma unroll
    for (int p = 0; p < 4; p++) {
        issueA(p * 32, p);
        issueB(p * 32, p);
        CP_COMMIT();
    }

    for (int i = 0; i < NKIT2; i++) {
        const int p = i % NSTG;
        // group g(i) holds stage p's data; ≤3 outstanding completes it
        CP_WAIT3();
        __syncthreads();

        const uint32_t aoff = (uint32_t)(p * ASTG_BYTES);
        const uint32_t boff = (uint32_t)(p * BSTG_BYTES);
        uint32_t af[2][4][4], bf[2][2][4];
        #pragma unroll
        for (int ks = 0; ks < 2; ks++) {
            #pragma unroll
            for (int im = 0; im < 4; im++)
                ldsm4t(af[ks][im], aA0[im] + aoff + ks * (16 * APADH * 2));
            #pragma unroll
            for (int bg = 0; bg < 2; bg++)
                ldsm4(bf[ks][bg], aB0[bg] + boff + ks * 32);
        }

        if (i + 4 < NKIT2) {
            const int pn = (i + 4) % NSTG;
            issueA((i + 4) * 32, pn);
            issueB((i + 4) * 32, pn);
        }
        CP_COMMIT();   // always commit (possibly empty) to keep group accounting fixed

        #pragma unroll
        for (int ks = 0; ks < 2; ks++)
            #pragma unroll
            for (int im = 0; im < 4; im++)
                #pragma unroll
                for (int in = 0; in < 4; in++)
                    mma_f16(acc[im][in], af[ks][im],
                            bf[ks][in >> 1][in & 1], bf[ks][in >> 1][(in & 1) + 2]);
    }

    if (MODE == 0) {
        #pragma unroll
        for (int im = 0; im < 4; im++) {
            const int r_lo = wm + im * 16 + lq;
            const int r_hi = r_lo + 8;
            #pragma unroll
            for (int in = 0; in < 4; in++) {
                const int col = n0 + wn + in * 8 + lr * 2;
                const float b0 = bias[col], b1 = bias[col + 1];
                __half2 vlo = __floats2half2_rn(acc[im][in][0] + b0, acc[im][in][1] + b1);
                __half2 vhi = __floats2half2_rn(acc[im][in][2] + b0, acc[im][in][3] + b1);
                *(__half2*)(g_qkv_h + (size_t)(m0 + r_lo) * Nn + col) = vlo;
                *(__half2*)(g_qkv_h + (size_t)(m0 + r_hi) * Nn + col) = vhi;
            }
        }
    } else {
        __syncthreads();
        #pragma unroll
        for (int pass = 0; pass < 2; pass++) {
            #pragma unroll
            for (int im = 0; im < 4; im++) {
                #pragma unroll
                for (int inl = 0; inl < 2; inl++) {
                    const int in = pass * 2 + inl;
                    const int cp = inl * 8 + lr * 2;
                    stg[wid][cp][im * 16 + lq]         = acc[im][in][0];
                    stg[wid][cp + 1][im * 16 + lq]     = acc[im][in][1];
                    stg[wid][cp][im * 16 + lq + 8]     = acc[im][in][2];
                    stg[wid][cp + 1][im * 16 + lq + 8] = acc[im][in][3];
                }
            }
            __syncwarp();
            #pragma unroll
            for (int c = 0; c < 16; c++) {
                const int col = n0 + wn + pass * 16 + c;
                const float b = bias[col];
                size_t o = ((size_t)(t * CC + col)) * SS + s0 + wm + lane * 2;
                float2 v  = *(float2*)&stg[wid][c][lane * 2];
                float2 xr = *(const float2*)(x + o);
                *(float2*)(Cout + o) = make_float2(v.x + b + xr.x, v.y + b + xr.y);
            }
            __syncwarp();
        }
    }
}

// ---------------- 3) attention: one WARP per (head, s); 8 s per block ----------------
#define QSTRIDE 200
#define ATTN_SMEM (8 * 16 * QSTRIDE * 2)

__global__ __launch_bounds__(256)
void attn_kernel(const float* __restrict__ qs, const float* __restrict__ qb,
                 const float* __restrict__ ks, const float* __restrict__ kb,
                 const float* __restrict__ relb) {
    extern __shared__ __half sh[];
    const int head  = blockIdx.x;
    const int sbase = blockIdx.y * 8;
    const int tid   = threadIdx.x;
    const int w     = tid >> 5;
    const int lane  = tid & 31;
    const int s     = sbase + w;

    __half* Q = sh + w * 16 * QSTRIDE;

    {
        const __half* src = g_qkv_h + (size_t)s * NQKV + head * 192;
        #pragma unroll
        for (int m = lane; m < 384; m += 32) {
            int tt = m / 24, off = (m % 24) * 8;
            *(uint4*)(Q + tt * QSTRIDE + off) =
                *(const uint4*)(src + (size_t)tt * SS * NQKV + off);
        }
    }
    __syncwarp();

    {
        int r = lane & 15, which = lane >> 4;
        __half* p = Q + r * QSTRIDE + which * 64;
        float v[64];
        float sum = 0.f, ssq = 0.f;
        #pragma unroll
        for (int q8 = 0; q8 < 8; q8++) {
            uint4 u = *(uint4*)(p + q8 * 8);
            __half2* hp = (__half2*)&u;
            #pragma unroll
            for (int j = 0; j < 4; j++) {
                float2 f = __half22float2(hp[j]);
                v[q8 * 8 + j * 2]     = f.x;
                v[q8 * 8 + j * 2 + 1] = f.y;
                sum += f.x + f.y;
                ssq += f.x * f.x + f.y * f.y;
            }
        }
        float mu  = sum * (1.0f / 64.0f);
        float var = ssq * (1.0f / 64.0f) - mu * mu;
        float inv = rsqrtf(var + 1e-6f);
        const float* sc = which ? ks : qs;
        const float* bi = which ? kb : qb;
        #pragma unroll
        for (int q8 = 0; q8 < 8; q8++) {
            uint32_t o[4];
            #pragma unroll
            for (int j = 0; j < 4; j++) {
                int c = q8 * 8 + j * 2;
                o[j] = packh((v[c] - mu) * inv * sc[c] + bi[c],
                             (v[c + 1] - mu) * inv * sc[c + 1] + bi[c + 1]);
            }
            *(uint4*)(p + q8 * 8) = *(uint4*)o;
        }
    }
    __syncwarp();

    const int i  = lane >> 1;
    const int j0 = (lane & 1) * 8;
    float wgt[8];
    {
        float qv[64];
        const __half* qp = Q + i * QSTRIDE;
        #pragma unroll
        for (int q8 = 0; q8 < 8; q8++) {
            uint4 u = *(const uint4*)(qp + q8 * 8);
            __half2* hp = (__half2*)&u;
            #pragma unroll
            for (int j = 0; j < 4; j++) {
                float2 f = __half22float2(hp[j]);
                qv[q8 * 8 + j * 2] = f.x; qv[q8 * 8 + j * 2 + 1] = f.y;
            }
        }
        float scv[8];
        #pragma unroll
        for (int jj = 0; jj < 8; jj++) {
            int j = j0 + jj;
            const __half* kp = Q + j * QSTRIDE + 64;
            float dot = 0.f;
            #pragma unroll
            for (int q8 = 0; q8 < 8; q8++) {
                uint4 u = *(const uint4*)(kp + q8 * 8);
                __half2* hp = (__half2*)&u;
                #pragma unroll
                for (int c = 0; c < 4; c++) {
                    float2 f = __half22float2(hp[c]);
                    dot += qv[q8 * 8 + c * 2] * f.x + qv[q8 * 8 + c * 2 + 1] * f.y;
                }
            }
            int rp = j - i;
            int bucket = (rp > 0) ? 16 : 0;
            int n = abs(rp);
            if (n < 8) bucket += n;
            else {
                int large = 8 + (int)(__logf((float)n * 0.125f) * (8.0f / 2.7725887222397811f));
                bucket += (large < 15) ? large : 15;
            }
            scv[jj] = dot * 0.125f + relb[bucket * NHEAD + head];
        }
        float mx = scv[0];
        #pragma unroll
        for (int jj = 1; jj < 8; jj++) mx = fmaxf(mx, scv[jj]);
        mx = fmaxf(mx, __shfl_xor_sync(0xffffffffu, mx, 1));
        float sm = 0.f;
        #pragma unroll
        for (int jj = 0; jj < 8; jj++) { wgt[jj] = __expf(scv[jj] - mx); sm += wgt[jj]; }
        sm += __shfl_xor_sync(0xffffffffu, sm, 1);
        float r = 1.0f / sm;
        #pragma unroll
        for (int jj = 0; jj < 8; jj++) wgt[jj] *= r;
    }

    {
        float outp[64];
        #pragma unroll
        for (int c = 0; c < 64; c++) outp[c] = 0.f;
        #pragma unroll
        for (int u = 0; u < 8; u++) {
            const __half* vp = Q + (j0 + u) * QSTRIDE + 128;
            float wv = wgt[u];
            #pragma unroll
            for (int q8 = 0; q8 < 8; q8++) {
                uint4 uu = *(const uint4*)(vp + q8 * 8);
                __half2* hp = (__half2*)&uu;
                #pragma unroll
                for (int c = 0; c < 4; c++) {
                    float2 f = __half22float2(hp[c]);
                    outp[q8 * 8 + c * 2]     += wv * f.x;
                    outp[q8 * 8 + c * 2 + 1] += wv * f.y;
                }
            }
        }
        #pragma unroll
        for (int c = 0; c < 64; c++)
            outp[c] += __shfl_xor_sync(0xffffffffu, outp[c], 1);
        if (!(lane & 1)) {
            #pragma unroll
            for (int q8 = 0; q8 < 8; q8++) {
                uint32_t o[4];
                #pragma unroll
                for (int j = 0; j < 4; j++)
                    o[j] = packh(outp[q8 * 8 + j * 2], outp[q8 * 8 + j * 2 + 1]);
                *(uint4*)(Q + i * QSTRIDE + q8 * 8) = *(uint4*)o;
            }
        }
    }
    __syncthreads();

    for (int idx = tid; idx < 16 * 64; idx += 256) {
        int t_ = idx >> 6;
        int c  = idx & 63;
        __half h[8];
        #pragma unroll
        for (int w2 = 0; w2 < 8; w2++)
            h[w2] = sh[w2 * 16 * QSTRIDE + t_ * QSTRIDE + c];
        *(uint4*)(g_att_h + ((size_t)(t_ * CC + head * 64 + c)) * SS + sbase) = *(uint4*)h;
    }
}

extern "C" void kernel_launch(void* const* d_in, const int* in_sizes, int n_in,
                              void* d_out, int out_size) {
    const float* x    = (const float*)d_in[0];
    const float* w1   = (const float*)d_in[1];
    const float* Win  = (const float*)d_in[2];
    const float* binq = (const float*)d_in[3];
    const float* qsc  = (const float*)d_in[4];
    const float* qbi  = (const float*)d_in[5];
    const float* ksc  = (const float*)d_in[6];
    const float* kbi  = (const float*)d_in[7];
    const float* relb = (const float*)d_in[8];
    const float* Wout = (const float*)d_in[9];
    const float* bout = (const float*)d_in[10];
    float* out = (float*)d_out;

    __half *wh_in_p, *wh_out_p;
    cudaGetSymbolAddress((void**)&wh_in_p, g_wh_in);
    cudaGetSymbolAddress((void**)&wh_out_p, g_wh_out);
    cudaFuncSetAttribute(attn_kernel, cudaFuncAttributeMaxDynamicSharedMemorySize, ATTN_SMEM);
    cudaFuncSetAttribute(mma_gemm<0>, cudaFuncAttributeMaxDynamicSharedMemorySize, GEMM_SMEM);
    cudaFuncSetAttribute(mma_gemm<1>, cudaFuncAttributeMaxDynamicSharedMemorySize, GEMM_SMEM);

    rms_conv_kernel<<<TT * NHEAD, 256>>>(x, w1);
    convw_kernel<<<(N4_IN + N4_OUT + 255) / 256, 256>>>(Win, wh_in_p, Wout, wh_out_p);
    mma_gemm<0><<<dim3(NQKV / 128, 32768 / 128), 256, GEMM_SMEM>>>(x, binq, nullptr, NQKV);
    attn_kernel<<<dim3(NHEAD, SS / 8), 256, ATTN_SMEM>>>(qsc, qbi, ksc, kbi, relb);
    mma_gemm<1><<<dim3(CC / 128, 32768 / 128), 256, GEMM_SMEM>>>(x, bout, out, CC);
}

// round 17
// speedup vs baseline: 1.2302x; 1.0669x over previous
#include <cuda_runtime.h>
#include <cuda_fp16.h>
#include <cstdint>

#define TT 16
#define CC 768
#define SS 2048
#define NHEAD 12
#define HDIM 64
#define NQKV 2304

// Scratch (device globals; no allocation allowed)
__device__ __half g_xh[(size_t)TT * CC * SS];          // fp16(x * invrms * w1), [t][k][s]
__device__ __half g_wh_in[(size_t)NQKV * CC];          // fp16(Win)
__device__ __half g_wh_out[(size_t)CC * CC];           // fp16(Wout)
__device__ __half g_qkv_h[(size_t)32768 * NQKV];       // [m=t*2048+s][n] fp16
__device__ __half g_att_h[(size_t)TT * CC * SS];       // [t][c][s] fp16

__device__ __forceinline__ uint32_t packh(float lo, float hi) {
    __half2 h = __floats2half2_rn(lo, hi);
    return *(uint32_t*)&h;
}

__device__ __forceinline__ void mma_f16(float* d, const uint32_t* a, uint32_t b0, uint32_t b1) {
    asm volatile(
        "mma.sync.aligned.m16n8k16.row.col.f32.f16.f16.f32 "
        "{%0,%1,%2,%3}, {%4,%5,%6,%7}, {%8,%9}, {%0,%1,%2,%3};"
        : "+f"(d[0]), "+f"(d[1]), "+f"(d[2]), "+f"(d[3])
        : "r"(a[0]), "r"(a[1]), "r"(a[2]), "r"(a[3]), "r"(b0), "r"(b1));
}

__device__ __forceinline__ void cp16(uint32_t dst, const void* src) {
    asm volatile("cp.async.cg.shared.global [%0], [%1], 16;" :: "r"(dst), "l"(src));
}
#define CP_COMMIT() asm volatile("cp.async.commit_group;" ::: "memory")
#define CP_WAIT3()  asm volatile("cp.async.wait_group 3;" ::: "memory")

__device__ __forceinline__ void ldsm4(uint32_t* r, uint32_t addr) {
    asm volatile("ldmatrix.sync.aligned.m8n8.x4.shared.b16 {%0,%1,%2,%3}, [%4];"
        : "=r"(r[0]), "=r"(r[1]), "=r"(r[2]), "=r"(r[3]) : "r"(addr));
}
__device__ __forceinline__ void ldsm4t(uint32_t* r, uint32_t addr) {
    asm volatile("ldmatrix.sync.aligned.m8n8.x4.trans.shared.b16 {%0,%1,%2,%3}, [%4];"
        : "=r"(r[0]), "=r"(r[1]), "=r"(r[2]), "=r"(r[3]) : "r"(addr));
}

// ---------------- 1) group RMS + fp16 conversion (fused) ----------------
__global__ __launch_bounds__(256)
void rms_conv_kernel(const float* __restrict__ x, const float* __restrict__ w1) {
    int b = blockIdx.x;
    int t = b / NHEAD, g = b - t * NHEAD;
    const float4* p = (const float4*)(x + (size_t)b * 64 * SS);
    float s = 0.f;
    for (int i = threadIdx.x; i < (64 * SS) / 4; i += 256) {
        float4 v = p[i];
        s += v.x * v.x + v.y * v.y + v.z * v.z + v.w * v.w;
    }
    #pragma unroll
    for (int m = 16; m; m >>= 1) s += __shfl_xor_sync(0xffffffffu, s, m);
    __shared__ float red[8];
    __shared__ float s_inv;
    if ((threadIdx.x & 31) == 0) red[threadIdx.x >> 5] = s;
    __syncthreads();
    if (threadIdx.x == 0) {
        float tot = 0.f;
        #pragma unroll
        for (int j = 0; j < 8; j++) tot += red[j];
        s_inv = rsqrtf(tot * (1.0f / (64.0f * SS)) + 1e-6f);
    }
    __syncthreads();
    const float inv = s_inv;

    for (int i = threadIdx.x; i < (64 * SS) / 8; i += 256) {
        int row = i >> 8;
        int off = (i & 255) * 8;
        float sc = inv * w1[g * 64 + row];
        const float4* src = (const float4*)(x + ((size_t)b * 64 + row) * SS + off);
        float4 a = src[0], c = src[1];
        uint32_t o[4] = {packh(a.x * sc, a.y * sc), packh(a.z * sc, a.w * sc),
                         packh(c.x * sc, c.y * sc), packh(c.z * sc, c.w * sc)};
        *(uint4*)(g_xh + ((size_t)(t * CC + g * 64 + row)) * SS + off) = *(uint4*)o;
    }
}

// ---------------- 1c) prep: both fp16 weight copies in one launch ----------------
#define N4_IN  (NQKV * CC / 4)
#define N4_OUT (CC * CC / 4)
__global__ __launch_bounds__(256)
void convw_kernel(const float* __restrict__ srcA, __half* __restrict__ dstA,
                  const float* __restrict__ srcB, __half* __restrict__ dstB) {
    int i = blockIdx.x * blockDim.x + threadIdx.x;
    const float* src;
    __half* dst;
    int j;
    if (i < N4_IN) { src = srcA; dst = dstA; j = i; }
    else if (i < N4_IN + N4_OUT) { src = srcB; dst = dstB; j = i - N4_IN; }
    else return;
    float4 v = ((const float4*)src)[j];
    uint32_t o[2] = {packh(v.x, v.y), packh(v.z, v.w)};
    *(uint2*)(dst + (size_t)j * 4) = *(uint2*)o;
}

// ---------------- 2/4) mma.sync fp16 GEMM, 5-stage cp.async ----------------
#define NKIT2 24
#define APADH 136
#define BPADH 40
#define ASTG_BYTES (32 * APADH * 2)         // 8704
#define BSTG_BYTES (128 * BPADH * 2)        // 10240
#define NSTG 5
#define GEMM_SMEM (NSTG * (ASTG_BYTES + BSTG_BYTES))   // 94720

template <int MODE>
__global__ __launch_bounds__(256, 2)
void mma_gemm(const float* __restrict__ x, const float* __restrict__ bias,
              float* __restrict__ Cout, int Nn) {
    extern __shared__ __align__(16) char smem_raw[];
    __half (*As)[32][APADH]  = (__half (*)[32][APADH])smem_raw;
    __half (*Bs)[128][BPADH] = (__half (*)[128][BPADH])(smem_raw + NSTG * ASTG_BYTES);
    float (*stg)[16][68]     = (float (*)[16][68])smem_raw;   // MODE 1 epilogue overlay

    const int tid  = threadIdx.x;
    const int wid  = tid >> 5;
    const int lane = tid & 31;
    const int wm   = (wid & 1) * 64;
    const int wn   = (wid >> 1) * 32;
    const int lq   = lane >> 2;
    const int lr   = lane & 3;

    const int m0 = blockIdx.y * 128;
    const int n0 = blockIdx.x * 128;
    const int t  = m0 >> 11;
    const int s0 = m0 & 2047;

    const __half* Asrc = (MODE == 0) ? g_xh : g_att_h;
    const __half* Bsrc = (MODE == 0) ? g_wh_in : g_wh_out;

    const int kA_l = ((lane >> 4) << 3) + (lane & 7);
    const int mOff = (((lane >> 3) & 1) << 3);
    const int nB_l = (((lane >> 3) & 1) << 3) + (lane & 7);
    const int kB_l = ((lane >> 4) << 3);
    uint32_t aA0[4], aB0[2];
    #pragma unroll
    for (int im = 0; im < 4; im++)
        aA0[im] = (uint32_t)__cvta_generic_to_shared(&As[0][kA_l][wm + im * 16 + mOff]);
    #pragma unroll
    for (int bg = 0; bg < 2; bg++)
        aB0[bg] = (uint32_t)__cvta_generic_to_shared(&Bs[0][wn + bg * 16 + nB_l][kB_l]);

    float acc[4][4][4];
    #pragma unroll
    for (int i = 0; i < 4; i++)
        #pragma unroll
        for (int j = 0; j < 4; j++)
            #pragma unroll
            for (int c = 0; c < 4; c++) acc[i][j][c] = 0.f;

    auto issueA = [&](int k0, int p) {
        #pragma unroll
        for (int r = 0; r < 2; r++) {
            int o = tid * 2 + r;
            int row = o >> 4;
            int ch  = (o & 15) * 8;
            cp16((uint32_t)__cvta_generic_to_shared(&As[p][row][ch]),
                 Asrc + ((size_t)(t * CC + k0 + row)) * SS + s0 + ch);
        }
    };
    auto issueB = [&](int k0, int p) {
        #pragma unroll
        for (int r = 0; r < 2; r++) {
            int o = tid * 2 + r;
            int row = o >> 2;
            int ch  = (o & 3) * 8;
            cp16((uint32_t)__cvta_generic_to_shared(&Bs[p][row][ch]),
                 Bsrc + (size_t)(n0 + row) * CC + k0 + ch);
        }
    };

    #pragma unroll
    for (int p = 0; p < 4; p++) {
        issueA(p * 32, p);
        issueB(p * 32, p);
        CP_COMMIT();
    }

    for (int i = 0; i < NKIT2; i++) {
        const int p = i % NSTG;
        CP_WAIT3();
        __syncthreads();

        const uint32_t aoff = (uint32_t)(p * ASTG_BYTES);
        const uint32_t boff = (uint32_t)(p * BSTG_BYTES);
        uint32_t af[2][4][4], bf[2][2][4];
        #pragma unroll
        for (int ks = 0; ks < 2; ks++) {
            #pragma unroll
            for (int im = 0; im < 4; im++)
                ldsm4t(af[ks][im], aA0[im] + aoff + ks * (16 * APADH * 2));
            #pragma unroll
            for (int bg = 0; bg < 2; bg++)
                ldsm4(bf[ks][bg], aB0[bg] + boff + ks * 32);
        }

        if (i + 4 < NKIT2) {
            const int pn = (i + 4) % NSTG;
            issueA((i + 4) * 32, pn);
            issueB((i + 4) * 32, pn);
        }
        CP_COMMIT();

        #pragma unroll
        for (int ks = 0; ks < 2; ks++)
            #pragma unroll
            for (int im = 0; im < 4; im++)
                #pragma unroll
                for (int in = 0; in < 4; in++)
                    mma_f16(acc[im][in], af[ks][im],
                            bf[ks][in >> 1][in & 1], bf[ks][in >> 1][(in & 1) + 2]);
    }

    if (MODE == 0) {
        #pragma unroll
        for (int im = 0; im < 4; im++) {
            const int r_lo = wm + im * 16 + lq;
            const int r_hi = r_lo + 8;
            #pragma unroll
            for (int in = 0; in < 4; in++) {
                const int col = n0 + wn + in * 8 + lr * 2;
                const float b0 = bias[col], b1 = bias[col + 1];
                __half2 vlo = __floats2half2_rn(acc[im][in][0] + b0, acc[im][in][1] + b1);
                __half2 vhi = __floats2half2_rn(acc[im][in][2] + b0, acc[im][in][3] + b1);
                *(__half2*)(g_qkv_h + (size_t)(m0 + r_lo) * Nn + col) = vlo;
                *(__half2*)(g_qkv_h + (size_t)(m0 + r_hi) * Nn + col) = vhi;
            }
        }
    } else {
        __syncthreads();
        #pragma unroll
        for (int pass = 0; pass < 2; pass++) {
            #pragma unroll
            for (int im = 0; im < 4; im++) {
                #pragma unroll
                for (int inl = 0; inl < 2; inl++) {
                    const int in = pass * 2 + inl;
                    const int cp = inl * 8 + lr * 2;
                    stg[wid][cp][im * 16 + lq]         = acc[im][in][0];
                    stg[wid][cp + 1][im * 16 + lq]     = acc[im][in][1];
                    stg[wid][cp][im * 16 + lq + 8]     = acc[im][in][2];
                    stg[wid][cp + 1][im * 16 + lq + 8] = acc[im][in][3];
                }
            }
            __syncwarp();
            #pragma unroll
            for (int c = 0; c < 16; c++) {
                const int col = n0 + wn + pass * 16 + c;
                const float b = bias[col];
                size_t o = ((size_t)(t * CC + col)) * SS + s0 + wm + lane * 2;
                float2 v  = *(float2*)&stg[wid][c][lane * 2];
                float2 xr = *(const float2*)(x + o);
                *(float2*)(Cout + o) = make_float2(v.x + b + xr.x, v.y + b + xr.y);
            }
            __syncwarp();
        }
    }
}

// ---------------- 3) attention: tensor-core, one WARP per (head, s) ----------------
#define QSTRIDE 200
#define ATTN_SMEM (8 * 16 * QSTRIDE * 2)

__global__ __launch_bounds__(256)
void attn_kernel(const float* __restrict__ qs, const float* __restrict__ qb,
                 const float* __restrict__ ks, const float* __restrict__ kb,
                 const float* __restrict__ relb) {
    extern __shared__ __half sh[];
    const int head  = blockIdx.x;
    const int sbase = blockIdx.y * 8;
    const int tid   = threadIdx.x;
    const int w     = tid >> 5;
    const int lane  = tid & 31;
    const int s     = sbase + w;

    __half* Q = sh + w * 16 * QSTRIDE;

    // load 16 x 192 halves
    {
        const __half* src = g_qkv_h + (size_t)s * NQKV + head * 192;
        #pragma unroll
        for (int m = lane; m < 384; m += 32) {
            int tt = m / 24, off = (m % 24) * 8;
            *(uint4*)(Q + tt * QSTRIDE + off) =
                *(const uint4*)(src + (size_t)tt * SS * NQKV + off);
        }
    }
    __syncwarp();

    // LN: lane handles one (row, q|k) pair fully
    {
        int r = lane & 15, which = lane >> 4;
        __half* p = Q + r * QSTRIDE + which * 64;
        float v[64];
        float sum = 0.f, ssq = 0.f;
        #pragma unroll
        for (int q8 = 0; q8 < 8; q8++) {
            uint4 u = *(uint4*)(p + q8 * 8);
            __half2* hp = (__half2*)&u;
            #pragma unroll
            for (int j = 0; j < 4; j++) {
                float2 f = __half22float2(hp[j]);
                v[q8 * 8 + j * 2]     = f.x;
                v[q8 * 8 + j * 2 + 1] = f.y;
                sum += f.x + f.y;
                ssq += f.x * f.x + f.y * f.y;
            }
        }
        float mu  = sum * (1.0f / 64.0f);
        float var = ssq * (1.0f / 64.0f) - mu * mu;
        float inv = rsqrtf(var + 1e-6f);
        const float* sc = which ? ks : qs;
        const float* bi = which ? kb : qb;
        #pragma unroll
        for (int q8 = 0; q8 < 8; q8++) {
            uint32_t o[4];
            #pragma unroll
            for (int j = 0; j < 4; j++) {
                int c = q8 * 8 + j * 2;
                o[j] = packh((v[c] - mu) * inv * sc[c] + bi[c],
                             (v[c + 1] - mu) * inv * sc[c + 1] + bi[c + 1]);
            }
            *(uint4*)(p + q8 * 8) = *(uint4*)o;
        }
    }
    __syncwarp();

    const int lq = lane >> 2;
    const int lr = lane & 3;

    // ldmatrix row pointers: lane -> row (l&7)+8*((l>>3)&1), col-half (l>>4)*8
    const int rowL = (lane & 7) + ((lane >> 3) & 1) * 8;
    const int colL = (lane >> 4) * 8;
    const uint32_t base = (uint32_t)__cvta_generic_to_shared(Q + rowL * QSTRIDE + colL);

    // Q a-frags (non-trans): qf[kc] = {a0,a1,a2,a3}
    uint32_t qf[4][4], kf[4][4], vf[4][4];
    #pragma unroll
    for (int kc = 0; kc < 4; kc++) ldsm4(qf[kc], base + kc * 32);
    // K b-frags (non-trans): kf[kc] = {nh0.b0, nh1.b0, nh0.b1, nh1.b1}
    #pragma unroll
    for (int kc = 0; kc < 4; kc++) ldsm4(kf[kc], base + 128 + kc * 32);
    // V b-frags (trans): vf[dgp] = {b0(2dgp), b1(2dgp), b0(2dgp+1), b1(2dgp+1)}
    #pragma unroll
    for (int dgp = 0; dgp < 4; dgp++) ldsm4t(vf[dgp], base + 256 + dgp * 32);

    // S = Q K^T (16x16), fp32
    float sfr[2][4];
    #pragma unroll
    for (int nh = 0; nh < 2; nh++)
        #pragma unroll
        for (int c = 0; c < 4; c++) sfr[nh][c] = 0.f;
    #pragma unroll
    for (int kc = 0; kc < 4; kc++)
        #pragma unroll
        for (int nh = 0; nh < 2; nh++)
            mma_f16(sfr[nh], qf[kc], kf[kc][nh], kf[kc][nh + 2]);

    // bias + softmax on fragments
    auto relbias = [&](int i, int j) -> float {
        int rp = j - i;
        int bucket = (rp > 0) ? 16 : 0;
        int n = abs(rp);
        if (n < 8) bucket += n;
        else {
            int large = 8 + (int)(__logf((float)n * 0.125f) * (8.0f / 2.7725887222397811f));
            bucket += (large < 15) ? large : 15;
        }
        return relb[bucket * NHEAD + head];
    };
    // entries: sfr[nh][0]=(lq, nh*8+2lr) [1]=+1col [2]=(lq+8, nh*8+2lr) [3]=+1col
    #pragma unroll
    for (int nh = 0; nh < 2; nh++) {
        sfr[nh][0] = sfr[nh][0] * 0.125f + relbias(lq,     nh * 8 + 2 * lr);
        sfr[nh][1] = sfr[nh][1] * 0.125f + relbias(lq,     nh * 8 + 2 * lr + 1);
        sfr[nh][2] = sfr[nh][2] * 0.125f + relbias(lq + 8, nh * 8 + 2 * lr);
        sfr[nh][3] = sfr[nh][3] * 0.125f + relbias(lq + 8, nh * 8 + 2 * lr + 1);
    }
    // row lq
    float mx0 = fmaxf(fmaxf(sfr[0][0], sfr[0][1]), fmaxf(sfr[1][0], sfr[1][1]));
    mx0 = fmaxf(mx0, __shfl_xor_sync(0xffffffffu, mx0, 1));
    mx0 = fmaxf(mx0, __shfl_xor_sync(0xffffffffu, mx0, 2));
    // row lq+8
    float mx1 = fmaxf(fmaxf(sfr[0][2], sfr[0][3]), fmaxf(sfr[1][2], sfr[1][3]));
    mx1 = fmaxf(mx1, __shfl_xor_sync(0xffffffffu, mx1, 1));
    mx1 = fmaxf(mx1, __shfl_xor_sync(0xffffffffu, mx1, 2));

    float e00 = __expf(sfr[0][0] - mx0), e01 = __expf(sfr[0][1] - mx0);
    float e10 = __expf(sfr[1][0] - mx0), e11 = __expf(sfr[1][1] - mx0);
    float f00 = __expf(sfr[0][2] - mx1), f01 = __expf(sfr[0][3] - mx1);
    float f10 = __expf(sfr[1][2] - mx1), f11 = __expf(sfr[1][3] - mx1);

    float sum0 = e00 + e01 + e10 + e11;
    sum0 += __shfl_xor_sync(0xffffffffu, sum0, 1);
    sum0 += __shfl_xor_sync(0xffffffffu, sum0, 2);
    float sum1 = f00 + f01 + f10 + f11;
    sum1 += __shfl_xor_sync(0xffffffffu, sum1, 1);
    sum1 += __shfl_xor_sync(0xffffffffu, sum1, 2);
    float r0 = 1.0f / sum0, r1 = 1.0f / sum1;

    // P a-frag (fp16): pf = {a0,a1,a2,a3}
    uint32_t pf[4];
    pf[0] = packh(e00 * r0, e01 * r0);   // (lq,   2lr..)  cols 0-7
    pf[1] = packh(f00 * r1, f01 * r1);   // (lq+8, 2lr..)  cols 0-7
    pf[2] = packh(e10 * r0, e11 * r0);   // (lq,   2lr+8)  cols 8-15
    pf[3] = packh(f10 * r1, f11 * r1);   // (lq+8, 2lr+8)

    // out = P V (16x64)
    float of[8][4];
    #pragma unroll
    for (int dg = 0; dg < 8; dg++) {
        #pragma unroll
        for (int c = 0; c < 4; c++) of[dg][c] = 0.f;
        mma_f16(of[dg], pf, vf[dg >> 1][(dg & 1) * 2], vf[dg >> 1][(dg & 1) * 2 + 1]);
    }

    // write out into the (now free) q slot: rows lq, lq+8; cols dg*8+2lr
    #pragma unroll
    for (int dg = 0; dg < 8; dg++) {
        *(__half2*)(Q + lq * QSTRIDE + dg * 8 + 2 * lr) =
            __floats2half2_rn(of[dg][0], of[dg][1]);
        *(__half2*)(Q + (lq + 8) * QSTRIDE + dg * 8 + 2 * lr) =
            __floats2half2_rn(of[dg][2], of[dg][3]);
    }
    __syncthreads();

    // transposed store: 8 s-consecutive halves per (t,c)
    for (int idx = tid; idx < 16 * 64; idx += 256) {
        int t_ = idx >> 6;
        int c  = idx & 63;
        __half h[8];
        #pragma unroll
        for (int w2 = 0; w2 < 8; w2++)
            h[w2] = sh[w2 * 16 * QSTRIDE + t_ * QSTRIDE + c];
        *(uint4*)(g_att_h + ((size_t)(t_ * CC + head * 64 + c)) * SS + sbase) = *(uint4*)h;
    }
}

extern "C" void kernel_launch(void* const* d_in, const int* in_sizes, int n_in,
                              void* d_out, int out_size) {
    const float* x    = (const float*)d_in[0];
    const float* w1   = (const float*)d_in[1];
    const float* Win  = (const float*)d_in[2];
    const float* binq = (const float*)d_in[3];
    const float* qsc  = (const float*)d_in[4];
    const float* qbi  = (const float*)d_in[5];
    const float* ksc  = (const float*)d_in[6];
    const float* kbi  = (const float*)d_in[7];
    const float* relb = (const float*)d_in[8];
    const float* Wout = (const float*)d_in[9];
    const float* bout = (const float*)d_in[10];
    float* out = (float*)d_out;

    __half *wh_in_p, *wh_out_p;
    cudaGetSymbolAddress((void**)&wh_in_p, g_wh_in);
    cudaGetSymbolAddress((void**)&wh_out_p, g_wh_out);
    cudaFuncSetAttribute(attn_kernel, cudaFuncAttributeMaxDynamicSharedMemorySize, ATTN_SMEM);
    cudaFuncSetAttribute(mma_gemm<0>, cudaFuncAttributeMaxDynamicSharedMemorySize, GEMM_SMEM);
    cudaFuncSetAttribute(mma_gemm<1>, cudaFuncAttributeMaxDynamicSharedMemorySize, GEMM_SMEM);

    rms_conv_kernel<<<TT * NHEAD, 256>>>(x, w1);
    convw_kernel<<<(N4_IN + N4_OUT + 255) / 256, 256>>>(Win, wh_in_p, Wout, wh_out_p);
    mma_gemm<0><<<dim3(NQKV / 128, 32768 / 128), 256, GEMM_SMEM>>>(x, binq, nullptr, NQKV);
    attn_kernel<<<dim3(NHEAD, SS / 8), 256, ATTN_SMEM>>>(qsc, qbi, ksc, kbi, relb);
    mma_gemm<1><<<dim3(CC / 128, 32768 / 128), 256, GEMM_SMEM>>>(x, bout, out, CC);
}